// round 16
// baseline (speedup 1.0000x reference)
#include <cuda_runtime.h>
#include <cuda_bf16.h>
#include <cstdint>

// Polynomial attention deg-2, B=2 H=16 S=2048 D=64 fp32.
// GEMM1: bf16 2-term split, mma.m16n8k16. GEMM2: tf32 m16n8k8, A-frags direct
// from GEMM1 accumulator via key-perm baked into V layout.
// Per-iteration software pipeline over the warp's two 16-row tiles:
//   GEMM1(t0) -> epi(t0) -> [GEMM2(t0) interleaved with GEMM1(t1)] ->
//   epi(t1) -> GEMM2(t1)
// so the tensor pipe sees a long dependency-free stream across the old
// GEMM1->GEMM2 join. Precomputed K/V scratch, cp.async staging.

#define NBH 32
#define SLEN 2048
#define DDIM 64
#define BM 256
#define BT 64
#define NITER (SLEN / BT)
#define EPS_CLAMP 1e-4f

#define LDQ2 36
#define LDK2 36
#define LDV 72

// smem offsets (4-byte units)
#define OF_QH 0
#define OF_QL (OF_QH + BM * LDQ2)
#define OF_KH (OF_QL + BM * LDQ2)          // [2][64][36] u32 (bf16 pairs)
#define OF_KL (OF_KH + 2 * BT * LDK2)
#define OF_V  (OF_KL + 2 * BT * LDK2)      // [2][64][72] f32 (rows permuted)
#define SMEM_U32 (OF_V + 2 * BT * LDV)
#define SMEM_BYTES (SMEM_U32 * 4)

// global scratch: packed bf16-pair splits of K, rna-rounded V
__device__ uint32_t g_KH[(size_t)NBH * SLEN * 32];
__device__ uint32_t g_KL[(size_t)NBH * SLEN * 32];
__device__ float    g_Vr[(size_t)NBH * SLEN * DDIM];

__device__ __forceinline__ float tf32_rna(float x) {
    uint32_t u;
    asm("cvt.rna.tf32.f32 %0, %1;" : "=r"(u) : "f"(x));
    return __uint_as_float(u);
}
__device__ __forceinline__ uint32_t packbf(float hi, float lo) {
    uint32_t u;
    asm("cvt.rn.bf16x2.f32 %0, %1, %2;" : "=r"(u) : "f"(hi), "f"(lo));
    return u;
}
__device__ __forceinline__ float bfrt(float x) {
    return __bfloat162float(__float2bfloat16(x));
}
__device__ __forceinline__ uint32_t smem_u32addr(const void* p) {
    uint32_t a;
    asm("{ .reg .u64 t; cvta.to.shared.u64 t, %1; cvt.u32.u64 %0, t; }"
        : "=r"(a) : "l"(p));
    return a;
}
__device__ __forceinline__ void cp16(uint32_t dst, const void* src) {
    asm volatile("cp.async.cg.shared.global [%0], [%1], 16;"
                 :: "r"(dst), "l"(src));
}
__device__ __forceinline__ void mma16(float* d, const uint32_t* a, const uint32_t* b) {
    asm("mma.sync.aligned.m16n8k16.row.col.f32.bf16.bf16.f32 "
        "{%0,%1,%2,%3}, {%4,%5,%6,%7}, {%8,%9}, {%0,%1,%2,%3};"
        : "+f"(d[0]), "+f"(d[1]), "+f"(d[2]), "+f"(d[3])
        : "r"(a[0]), "r"(a[1]), "r"(a[2]), "r"(a[3]), "r"(b[0]), "r"(b[1]));
}
__device__ __forceinline__ void mma8(float* d, const uint32_t* a, const uint32_t* b) {
    asm("mma.sync.aligned.m16n8k8.row.col.f32.tf32.tf32.f32 "
        "{%0,%1,%2,%3}, {%4,%5,%6,%7}, {%8,%9}, {%0,%1,%2,%3};"
        : "+f"(d[0]), "+f"(d[1]), "+f"(d[2]), "+f"(d[3])
        : "r"(a[0]), "r"(a[1]), "r"(a[2]), "r"(a[3]), "r"(b[0]), "r"(b[1]));
}

// ---- precompute: K -> (KH,KL) packed bf16 pairs, V -> rna-rounded f32 ----
__global__ void precompute_kv(const float* __restrict__ k,
                              const float* __restrict__ v) {
    size_t i = (size_t)blockIdx.x * blockDim.x + threadIdx.x;
    const float4* k4 = (const float4*)k;
    const float4* v4 = (const float4*)v;
    uint4 H[2], L[2];
    uint32_t* hp = (uint32_t*)H;
    uint32_t* lp = (uint32_t*)L;
#pragma unroll
    for (int r = 0; r < 4; r++) {
        float4 x = k4[i * 4 + r];
        float h0 = bfrt(x.x), h1 = bfrt(x.y), h2 = bfrt(x.z), h3 = bfrt(x.w);
        hp[r * 2 + 0] = packbf(h1, h0);
        hp[r * 2 + 1] = packbf(h3, h2);
        lp[r * 2 + 0] = packbf(x.y - h1, x.x - h0);
        lp[r * 2 + 1] = packbf(x.w - h3, x.z - h2);
    }
    ((uint4*)g_KH)[i * 2 + 0] = H[0];
    ((uint4*)g_KH)[i * 2 + 1] = H[1];
    ((uint4*)g_KL)[i * 2 + 0] = L[0];
    ((uint4*)g_KL)[i * 2 + 1] = L[1];
#pragma unroll
    for (int r = 0; r < 4; r++) {
        float4 y = v4[i * 4 + r];
        y.x = tf32_rna(y.x); y.y = tf32_rna(y.y);
        y.z = tf32_rna(y.z); y.w = tf32_rna(y.w);
        ((float4*)g_Vr)[i * 4 + r] = y;
    }
}

__global__ void __launch_bounds__(256, 1)
poly_attn_mma(const float* __restrict__ q, float* __restrict__ out) {
    extern __shared__ uint32_t sm[];
    const uint32_t sb = smem_u32addr(sm);
    const int tid = threadIdx.x;
    const int wid = tid >> 5, lane = tid & 31;
    const int tq = lane >> 2, tc = lane & 3;
    const int bh = blockIdx.y, mt = blockIdx.x;
    const int m0 = wid * 32;

    // ---- Q tile [256][64] -> bf16 hi/lo pairs (once) ----
    {
        const float4* qg = (const float4*)(q + ((size_t)bh * SLEN + (size_t)mt * BM) * DDIM);
#pragma unroll
        for (int r = 0; r < 16; r++) {
            int i4 = tid + r * 256;
            int row = i4 >> 4, pr = (i4 & 15) * 2;
            float4 x = qg[i4];
            float h0 = bfrt(x.x), h1 = bfrt(x.y), h2 = bfrt(x.z), h3 = bfrt(x.w);
            *(uint2*)(sm + OF_QH + row * LDQ2 + pr) =
                make_uint2(packbf(h1, h0), packbf(h3, h2));
            *(uint2*)(sm + OF_QL + row * LDQ2 + pr) =
                make_uint2(packbf(x.y - h1, x.x - h0), packbf(x.w - h3, x.z - h2));
        }
    }

    // ---- async tile stage ----
    auto issue_tile = [&](int nt, int buf) {
        const uint32_t* gKH = g_KH + ((size_t)bh * SLEN + nt * BT) * 32;
        const uint32_t* gKL = g_KL + ((size_t)bh * SLEN + nt * BT) * 32;
        const float* gV = g_Vr + ((size_t)bh * SLEN + nt * BT) * DDIM;
#pragma unroll
        for (int j = 0; j < 2; j++) {
            int cc = tid + j * 256;
            int row = cc >> 3, o4 = (cc & 7) * 4;
            cp16(sb + (uint32_t)(OF_KH + buf * BT * LDK2 + row * LDK2 + o4) * 4,
                 gKH + row * 32 + o4);
            cp16(sb + (uint32_t)(OF_KL + buf * BT * LDK2 + row * LDK2 + o4) * 4,
                 gKL + row * 32 + o4);
        }
#pragma unroll
        for (int j = 0; j < 4; j++) {
            int cc = tid + j * 256;
            int row = cc >> 4, o4 = (cc & 15) * 4;
            int jj = row & 7;   // V row permutation (matches GEMM2 A-frag layout)
            int vrow = (row & ~7) | ((jj & 1) ? (4 + (jj >> 1)) : (jj >> 1));
            cp16(sb + (uint32_t)(OF_V + buf * BT * LDV + vrow * LDV + o4) * 4,
                 gV + row * DDIM + o4);
        }
        asm volatile("cp.async.commit_group;" ::: "memory");
    };

    issue_tile(0, 0);
    issue_tile(1, 1);
    asm volatile("cp.async.wait_group 1;" ::: "memory");   // tile 0 landed
    __syncthreads();

    float oacc[2][8][4];
    float dl[2] = {0.f, 0.f}, dh[2] = {0.f, 0.f};
#pragma unroll
    for (int t = 0; t < 2; t++)
#pragma unroll
        for (int ct = 0; ct < 8; ct++)
#pragma unroll
            for (int j = 0; j < 4; j++) oacc[t][ct][j] = 0.f;

    const int qoffh0 = OF_QH + (m0 + tq) * LDQ2 + tc;
    const int qoffl0 = OF_QL + (m0 + tq) * LDQ2 + tc;

    for (int nt = 0; nt < NITER; nt++) {
        const int buf = nt & 1;
        const int KHo = OF_KH + buf * BT * LDK2;
        const int KLo = OF_KL + buf * BT * LDK2;
        const int Vo  = OF_V  + buf * BT * LDV;

        float sacc0[8][4], sacc1[8][4];
#pragma unroll
        for (int ct = 0; ct < 8; ct++)
#pragma unroll
            for (int j = 0; j < 4; j++) { sacc0[ct][j] = 0.f; sacc1[ct][j] = 0.f; }

        // ---- GEMM1 one k-step for tile t into sacc (3 passes, bh2 cached) ----
        auto gemm1_ks = [&](float (&sacc)[8][4], int t, int ks) {
            const int ko = ks * 8;
            const int oh = qoffh0 + t * 16 * LDQ2 + ko;
            const int ol = qoffl0 + t * 16 * LDQ2 + ko;
            uint32_t ah[4], al[4];
            ah[0] = sm[oh];
            ah[1] = sm[oh + 8 * LDQ2];
            ah[2] = sm[oh + 4];
            ah[3] = sm[oh + 8 * LDQ2 + 4];
            al[0] = sm[ol];
            al[1] = sm[ol + 8 * LDQ2];
            al[2] = sm[ol + 4];
            al[3] = sm[ol + 8 * LDQ2 + 4];
            uint32_t bh2[8][2];
#pragma unroll
            for (int ct = 0; ct < 8; ct++) {
                const int o = KHo + (8 * ct + tq) * LDK2 + ko + tc;
                bh2[ct][0] = sm[o]; bh2[ct][1] = sm[o + 4];
                mma16(sacc[ct], ah, bh2[ct]);
            }
#pragma unroll
            for (int ct = 0; ct < 8; ct++) {
                const int o = KLo + (8 * ct + tq) * LDK2 + ko + tc;
                uint32_t bl2[2];
                bl2[0] = sm[o]; bl2[1] = sm[o + 4];
                mma16(sacc[ct], ah, bl2);
            }
#pragma unroll
            for (int ct = 0; ct < 8; ct++)
                mma16(sacc[ct], al, bh2[ct]);
        };

        // ---- GEMM2 one key-group g of tile t ----
        auto gemm2_g = [&](float (&oaccT)[8][4], float (&sacc)[8][4], int g) {
            uint32_t a[4];
            a[0] = __float_as_uint(sacc[g][0]);
            a[1] = __float_as_uint(sacc[g][2]);
            a[2] = __float_as_uint(sacc[g][1]);
            a[3] = __float_as_uint(sacc[g][3]);
            const int vk = Vo + (8 * g + tc) * LDV + tq;
#pragma unroll
            for (int ct = 0; ct < 8; ct++) {
                uint32_t vb[2];
                vb[0] = sm[vk + 8 * ct];
                vb[1] = sm[vk + 4 * LDV + 8 * ct];
                mma8(oaccT[ct], a, vb);
            }
        };

        auto epi = [&](float (&sacc)[8][4], int t) {
#pragma unroll
            for (int ct = 0; ct < 8; ct++) {
                sacc[ct][0] = tf32_rna(sacc[ct][0] * sacc[ct][0]);
                sacc[ct][1] = tf32_rna(sacc[ct][1] * sacc[ct][1]);
                sacc[ct][2] = tf32_rna(sacc[ct][2] * sacc[ct][2]);
                sacc[ct][3] = tf32_rna(sacc[ct][3] * sacc[ct][3]);
                dl[t] += sacc[ct][0] + sacc[ct][1];
                dh[t] += sacc[ct][2] + sacc[ct][3];
            }
        };

        // Stage 1: GEMM1(t0)
#pragma unroll
        for (int ks = 0; ks < 4; ks++) gemm1_ks(sacc0, 0, ks);
        // Stage 2: epilogue(t0)
        epi(sacc0, 0);
        // Stage 3: GEMM2(t0) interleaved with GEMM1(t1)
#pragma unroll
        for (int ks = 0; ks < 4; ks++) {
            gemm2_g(oacc[0], sacc0, 2 * ks);
            gemm1_ks(sacc1, 1, ks);
            gemm2_g(oacc[0], sacc0, 2 * ks + 1);
        }
        // Stage 4: epilogue(t1)
        epi(sacc1, 1);
        // Stage 5: GEMM2(t1)
#pragma unroll
        for (int g = 0; g < 8; g++) gemm2_g(oacc[1], sacc1, g);

        if (nt + 1 < NITER)
            asm volatile("cp.async.wait_group 0;" ::: "memory");  // tile nt+1 landed
        __syncthreads();
        if (nt + 2 < NITER) issue_tile(nt + 2, buf);
    }

    // ---- denominator reduce over tc lanes; normalize and store ----
    float* og = out + ((size_t)bh * SLEN + (size_t)mt * BM + m0) * DDIM;
#pragma unroll
    for (int t = 0; t < 2; t++) {
        float l = dl[t], h = dh[t];
        l += __shfl_xor_sync(0xffffffffu, l, 1);
        l += __shfl_xor_sync(0xffffffffu, l, 2);
        h += __shfl_xor_sync(0xffffffffu, h, 1);
        h += __shfl_xor_sync(0xffffffffu, h, 2);
        const float il = 1.f / fmaxf(l, EPS_CLAMP);
        const float ih = 1.f / fmaxf(h, EPS_CLAMP);
#pragma unroll
        for (int ct = 0; ct < 8; ct++) {
            int dcol = 8 * ct + 2 * tc;
            *(float2*)(og + (size_t)(t * 16 + tq) * DDIM + dcol) =
                make_float2(oacc[t][ct][0] * il, oacc[t][ct][1] * il);
            *(float2*)(og + (size_t)(t * 16 + tq + 8) * DDIM + dcol) =
                make_float2(oacc[t][ct][2] * ih, oacc[t][ct][3] * ih);
        }
    }
}

extern "C" void kernel_launch(void* const* d_in, const int* in_sizes, int n_in,
                              void* d_out, int out_size) {
    (void)in_sizes; (void)n_in; (void)out_size;
    const float* q = (const float*)d_in[0];
    const float* k = (const float*)d_in[1];
    const float* v = (const float*)d_in[2];
    float* out = (float*)d_out;

    precompute_kv<<<1024, 256>>>(k, v);

    cudaFuncSetAttribute(poly_attn_mma,
                         cudaFuncAttributeMaxDynamicSharedMemorySize, SMEM_BYTES);
    poly_attn_mma<<<dim3(SLEN / BM, NBH), 256, SMEM_BYTES>>>(q, out);
}

// round 17
// speedup vs baseline: 1.1013x; 1.1013x over previous
#include <cuda_runtime.h>
#include <cuda_bf16.h>
#include <cstdint>

// Polynomial attention deg-2, B=2 H=16 S=2048 D=64 fp32.
// GEMM1: bf16 2-term split, mma.m16n8k16 (3-pass). GEMM2: tf32 m16n8k8,
// A-frags direct from GEMM1 accumulator via key-perm baked into V layout.
// PERSISTENT 148-CTA grid: work = 256 tiles x 8 chunks (4 key-iters each),
// static contiguous ranges; split tiles combined pairwise via scratch+flag.

#define NBH 32
#define SLEN 2048
#define DDIM 64
#define BM 256
#define BT 64
#define NTILES 256          // 32 bh x 8 mt
#define NCHUNK 8            // chunks per tile
#define CH_ITERS 4          // key-iters per chunk
#define NJOBS (NTILES * NCHUNK)
#define NCTAS 148
#define EPS_CLAMP 1e-4f

#define LDQ2 36
#define LDK2 36
#define LDV 72

// smem offsets (4-byte units)
#define OF_QH 0
#define OF_QL (OF_QH + BM * LDQ2)
#define OF_KH (OF_QL + BM * LDQ2)
#define OF_KL (OF_KH + 2 * BT * LDK2)
#define OF_V  (OF_KL + 2 * BT * LDK2)
#define SMEM_U32 (OF_V + 2 * BT * LDV)
#define SMEM_BYTES (SMEM_U32 * 4)

// global scratch
__device__ uint32_t g_KH[(size_t)NBH * SLEN * 32];
__device__ uint32_t g_KL[(size_t)NBH * SLEN * 32];
__device__ float    g_Vr[(size_t)NBH * SLEN * DDIM];
__device__ float    g_scrN[(size_t)NTILES * BM * DDIM];   // partial numerators
__device__ float    g_scrD[(size_t)NTILES * BM];          // partial denominators
__device__ int      g_flag[NTILES];

__device__ __forceinline__ float tf32_rna(float x) {
    uint32_t u;
    asm("cvt.rna.tf32.f32 %0, %1;" : "=r"(u) : "f"(x));
    return __uint_as_float(u);
}
__device__ __forceinline__ uint32_t packbf(float hi, float lo) {
    uint32_t u;
    asm("cvt.rn.bf16x2.f32 %0, %1, %2;" : "=r"(u) : "f"(hi), "f"(lo));
    return u;
}
__device__ __forceinline__ float bfrt(float x) {
    return __bfloat162float(__float2bfloat16(x));
}
__device__ __forceinline__ uint32_t smem_u32addr(const void* p) {
    uint32_t a;
    asm("{ .reg .u64 t; cvta.to.shared.u64 t, %1; cvt.u32.u64 %0, t; }"
        : "=r"(a) : "l"(p));
    return a;
}
__device__ __forceinline__ void cp16(uint32_t dst, const void* src) {
    asm volatile("cp.async.cg.shared.global [%0], [%1], 16;"
                 :: "r"(dst), "l"(src));
}
__device__ __forceinline__ void mma16(float* d, const uint32_t* a, const uint32_t* b) {
    asm("mma.sync.aligned.m16n8k16.row.col.f32.bf16.bf16.f32 "
        "{%0,%1,%2,%3}, {%4,%5,%6,%7}, {%8,%9}, {%0,%1,%2,%3};"
        : "+f"(d[0]), "+f"(d[1]), "+f"(d[2]), "+f"(d[3])
        : "r"(a[0]), "r"(a[1]), "r"(a[2]), "r"(a[3]), "r"(b[0]), "r"(b[1]));
}
__device__ __forceinline__ void mma8(float* d, const uint32_t* a, const uint32_t* b) {
    asm("mma.sync.aligned.m16n8k8.row.col.f32.tf32.tf32.f32 "
        "{%0,%1,%2,%3}, {%4,%5,%6,%7}, {%8,%9}, {%0,%1,%2,%3};"
        : "+f"(d[0]), "+f"(d[1]), "+f"(d[2]), "+f"(d[3])
        : "r"(a[0]), "r"(a[1]), "r"(a[2]), "r"(a[3]), "r"(b[0]), "r"(b[1]));
}

// ---- precompute: K -> (KH,KL) packed bf16 pairs, V -> rna f32; zero flags ----
__global__ void precompute_kv(const float* __restrict__ k,
                              const float* __restrict__ v) {
    if (blockIdx.x == 0 && threadIdx.x < NTILES) g_flag[threadIdx.x] = 0;
    size_t i = (size_t)blockIdx.x * blockDim.x + threadIdx.x;
    const float4* k4 = (const float4*)k;
    const float4* v4 = (const float4*)v;
    uint4 H[2], L[2];
    uint32_t* hp = (uint32_t*)H;
    uint32_t* lp = (uint32_t*)L;
#pragma unroll
    for (int r = 0; r < 4; r++) {
        float4 x = k4[i * 4 + r];
        float h0 = bfrt(x.x), h1 = bfrt(x.y), h2 = bfrt(x.z), h3 = bfrt(x.w);
        hp[r * 2 + 0] = packbf(h1, h0);
        hp[r * 2 + 1] = packbf(h3, h2);
        lp[r * 2 + 0] = packbf(x.y - h1, x.x - h0);
        lp[r * 2 + 1] = packbf(x.w - h3, x.z - h2);
    }
    ((uint4*)g_KH)[i * 2 + 0] = H[0];
    ((uint4*)g_KH)[i * 2 + 1] = H[1];
    ((uint4*)g_KL)[i * 2 + 0] = L[0];
    ((uint4*)g_KL)[i * 2 + 1] = L[1];
#pragma unroll
    for (int r = 0; r < 4; r++) {
        float4 y = v4[i * 4 + r];
        y.x = tf32_rna(y.x); y.y = tf32_rna(y.y);
        y.z = tf32_rna(y.z); y.w = tf32_rna(y.w);
        ((float4*)g_Vr)[i * 4 + r] = y;
    }
}

__global__ void __launch_bounds__(256, 1)
poly_attn_mma(const float* __restrict__ q, float* __restrict__ out) {
    extern __shared__ uint32_t sm[];
    const uint32_t sb = smem_u32addr(sm);
    const int tid = threadIdx.x;
    const int wid = tid >> 5, lane = tid & 31;
    const int tq = lane >> 2, tc = lane & 3;
    const int m0 = wid * 32;
    const int c = blockIdx.x;

    const int s = (c * NJOBS) / NCTAS;
    const int e = ((c + 1) * NJOBS) / NCTAS;

    int j = s;
    while (j < e) {
        const int t = j >> 3;
        const int c0 = j & 7;
        const int c1 = min(NCHUNK, e - (t << 3));
        const bool firstPartial = (c0 != 0);   // earlier chunks owned by CTA c-1
        const bool lastPartial  = (c1 != NCHUNK); // later chunks owned by CTA c+1
        const int bh = t >> 3, mt = t & 7;
        const int it0 = c0 * CH_ITERS, it1 = c1 * CH_ITERS;

        __syncthreads();   // all warps done with previous segment's smem

        // ---- Q tile [256][64] -> bf16 hi/lo pairs ----
        {
            const float4* qg = (const float4*)(q + ((size_t)bh * SLEN + (size_t)mt * BM) * DDIM);
#pragma unroll
            for (int r = 0; r < 16; r++) {
                int i4 = tid + r * 256;
                int row = i4 >> 4, pr = (i4 & 15) * 2;
                float4 x = qg[i4];
                float h0 = bfrt(x.x), h1 = bfrt(x.y), h2 = bfrt(x.z), h3 = bfrt(x.w);
                *(uint2*)(sm + OF_QH + row * LDQ2 + pr) =
                    make_uint2(packbf(h1, h0), packbf(h3, h2));
                *(uint2*)(sm + OF_QL + row * LDQ2 + pr) =
                    make_uint2(packbf(x.y - h1, x.x - h0), packbf(x.w - h3, x.z - h2));
            }
        }

        auto issue_tile = [&](int nt, int buf) {
            const uint32_t* gKH = g_KH + ((size_t)bh * SLEN + nt * BT) * 32;
            const uint32_t* gKL = g_KL + ((size_t)bh * SLEN + nt * BT) * 32;
            const float* gV = g_Vr + ((size_t)bh * SLEN + nt * BT) * DDIM;
#pragma unroll
            for (int jj = 0; jj < 2; jj++) {
                int cc = tid + jj * 256;
                int row = cc >> 3, o4 = (cc & 7) * 4;
                cp16(sb + (uint32_t)(OF_KH + buf * BT * LDK2 + row * LDK2 + o4) * 4,
                     gKH + row * 32 + o4);
                cp16(sb + (uint32_t)(OF_KL + buf * BT * LDK2 + row * LDK2 + o4) * 4,
                     gKL + row * 32 + o4);
            }
#pragma unroll
            for (int jj = 0; jj < 4; jj++) {
                int cc = tid + jj * 256;
                int row = cc >> 4, o4 = (cc & 15) * 4;
                int rr = row & 7;   // key-perm for GEMM2 A-frag layout
                int vrow = (row & ~7) | ((rr & 1) ? (4 + (rr >> 1)) : (rr >> 1));
                cp16(sb + (uint32_t)(OF_V + buf * BT * LDV + vrow * LDV + o4) * 4,
                     gV + row * DDIM + o4);
            }
            asm volatile("cp.async.commit_group;" ::: "memory");
        };

        issue_tile(it0, 0);
        if (it0 + 1 < it1) {
            issue_tile(it0 + 1, 1);
            asm volatile("cp.async.wait_group 1;" ::: "memory");
        } else {
            asm volatile("cp.async.wait_group 0;" ::: "memory");
        }
        __syncthreads();

        float oacc[2][8][4];
        float dl[2] = {0.f, 0.f}, dh[2] = {0.f, 0.f};
#pragma unroll
        for (int t2 = 0; t2 < 2; t2++)
#pragma unroll
            for (int ct = 0; ct < 8; ct++)
#pragma unroll
                for (int jj = 0; jj < 4; jj++) oacc[t2][ct][jj] = 0.f;

        const int qoffh0 = OF_QH + (m0 + tq) * LDQ2 + tc;
        const int qoffl0 = OF_QL + (m0 + tq) * LDQ2 + tc;

        for (int nt = it0; nt < it1; nt++) {
            const int buf = (nt - it0) & 1;
            const int KHo = OF_KH + buf * BT * LDK2;
            const int KLo = OF_KL + buf * BT * LDK2;
            const int Vo  = OF_V  + buf * BT * LDV;

            float sacc[2][8][4];
#pragma unroll
            for (int t2 = 0; t2 < 2; t2++)
#pragma unroll
                for (int ct = 0; ct < 8; ct++)
#pragma unroll
                    for (int jj = 0; jj < 4; jj++) sacc[t2][ct][jj] = 0.f;

#pragma unroll
            for (int ks = 0; ks < 4; ks++) {
                const int ko = ks * 8;
                uint32_t ah[2][4], al[2][4];
#pragma unroll
                for (int t2 = 0; t2 < 2; t2++) {
                    const int oh = qoffh0 + t2 * 16 * LDQ2 + ko;
                    const int ol = qoffl0 + t2 * 16 * LDQ2 + ko;
                    ah[t2][0] = sm[oh];
                    ah[t2][1] = sm[oh + 8 * LDQ2];
                    ah[t2][2] = sm[oh + 4];
                    ah[t2][3] = sm[oh + 8 * LDQ2 + 4];
                    al[t2][0] = sm[ol];
                    al[t2][1] = sm[ol + 8 * LDQ2];
                    al[t2][2] = sm[ol + 4];
                    al[t2][3] = sm[ol + 8 * LDQ2 + 4];
                }
                uint32_t bh2[8][2];
#pragma unroll
                for (int ct = 0; ct < 8; ct++) {
                    const int o = KHo + (8 * ct + tq) * LDK2 + ko + tc;
                    bh2[ct][0] = sm[o]; bh2[ct][1] = sm[o + 4];
                    mma16(sacc[0][ct], ah[0], bh2[ct]);
                    mma16(sacc[1][ct], ah[1], bh2[ct]);
                }
#pragma unroll
                for (int ct = 0; ct < 8; ct++) {
                    const int o = KLo + (8 * ct + tq) * LDK2 + ko + tc;
                    uint32_t bl2[2];
                    bl2[0] = sm[o]; bl2[1] = sm[o + 4];
                    mma16(sacc[0][ct], ah[0], bl2);
                    mma16(sacc[1][ct], ah[1], bl2);
                }
#pragma unroll
                for (int ct = 0; ct < 8; ct++) {
                    mma16(sacc[0][ct], al[0], bh2[ct]);
                    mma16(sacc[1][ct], al[1], bh2[ct]);
                }
            }

#pragma unroll
            for (int t2 = 0; t2 < 2; t2++)
#pragma unroll
                for (int ct = 0; ct < 8; ct++) {
                    sacc[t2][ct][0] = tf32_rna(sacc[t2][ct][0] * sacc[t2][ct][0]);
                    sacc[t2][ct][1] = tf32_rna(sacc[t2][ct][1] * sacc[t2][ct][1]);
                    sacc[t2][ct][2] = tf32_rna(sacc[t2][ct][2] * sacc[t2][ct][2]);
                    sacc[t2][ct][3] = tf32_rna(sacc[t2][ct][3] * sacc[t2][ct][3]);
                    dl[t2] += sacc[t2][ct][0] + sacc[t2][ct][1];
                    dh[t2] += sacc[t2][ct][2] + sacc[t2][ct][3];
                }

#pragma unroll
            for (int g = 0; g < 8; g++) {
                uint32_t a[2][4];
#pragma unroll
                for (int t2 = 0; t2 < 2; t2++) {
                    a[t2][0] = __float_as_uint(sacc[t2][g][0]);
                    a[t2][1] = __float_as_uint(sacc[t2][g][2]);
                    a[t2][2] = __float_as_uint(sacc[t2][g][1]);
                    a[t2][3] = __float_as_uint(sacc[t2][g][3]);
                }
                const int vk = Vo + (8 * g + tc) * LDV + tq;
#pragma unroll
                for (int ct = 0; ct < 8; ct++) {
                    uint32_t vb[2];
                    vb[0] = sm[vk + 8 * ct];
                    vb[1] = sm[vk + 4 * LDV + 8 * ct];
                    mma8(oacc[0][ct], a[0], vb);
                    mma8(oacc[1][ct], a[1], vb);
                }
            }

            if (nt + 1 < it1)
                asm volatile("cp.async.wait_group 0;" ::: "memory");
            __syncthreads();
            if (nt + 2 < it1) issue_tile(nt + 2, (nt - it0) & 1);
        }

        // ---- segment epilogue: reduce denom over tc lanes ----
        float lr[2], hr[2];
#pragma unroll
        for (int t2 = 0; t2 < 2; t2++) {
            float l = dl[t2], h = dh[t2];
            l += __shfl_xor_sync(0xffffffffu, l, 1);
            l += __shfl_xor_sync(0xffffffffu, l, 2);
            h += __shfl_xor_sync(0xffffffffu, h, 1);
            h += __shfl_xor_sync(0xffffffffu, h, 2);
            lr[t2] = l; hr[t2] = h;
        }

        float* sN = g_scrN + (size_t)t * (BM * DDIM);
        float* sD = g_scrD + (size_t)t * BM;

        if (firstPartial) {
            // write partial numerator + denominator, then flag
#pragma unroll
            for (int t2 = 0; t2 < 2; t2++) {
                int row0 = m0 + t2 * 16 + tq;
#pragma unroll
                for (int ct = 0; ct < 8; ct++) {
                    int dcol = 8 * ct + 2 * tc;
                    *(float2*)(sN + (size_t)row0 * DDIM + dcol) =
                        make_float2(oacc[t2][ct][0], oacc[t2][ct][1]);
                    *(float2*)(sN + (size_t)(row0 + 8) * DDIM + dcol) =
                        make_float2(oacc[t2][ct][2], oacc[t2][ct][3]);
                }
                if (tc == 0) {
                    sD[row0] = lr[t2];
                    sD[row0 + 8] = hr[t2];
                }
            }
            __threadfence();
            __syncthreads();
            if (tid == 0) atomicExch(&g_flag[t], 1);
        } else {
            if (lastPartial) {
                // partner (CTA c+1) ran its chunks first; combine
                if (tid == 0) {
                    volatile int* f = &g_flag[t];
                    while (*f == 0) { }
                }
                __syncthreads();
                __threadfence();
#pragma unroll
                for (int t2 = 0; t2 < 2; t2++) {
                    int row0 = m0 + t2 * 16 + tq;
                    lr[t2] += sD[row0];
                    hr[t2] += sD[row0 + 8];
#pragma unroll
                    for (int ct = 0; ct < 8; ct++) {
                        int dcol = 8 * ct + 2 * tc;
                        float2 p0 = *(float2*)(sN + (size_t)row0 * DDIM + dcol);
                        float2 p1 = *(float2*)(sN + (size_t)(row0 + 8) * DDIM + dcol);
                        oacc[t2][ct][0] += p0.x; oacc[t2][ct][1] += p0.y;
                        oacc[t2][ct][2] += p1.x; oacc[t2][ct][3] += p1.y;
                    }
                }
            }
            // normalize and store
            float* og = out + ((size_t)bh * SLEN + (size_t)mt * BM + m0) * DDIM;
#pragma unroll
            for (int t2 = 0; t2 < 2; t2++) {
                const float il = 1.f / fmaxf(lr[t2], EPS_CLAMP);
                const float ih = 1.f / fmaxf(hr[t2], EPS_CLAMP);
#pragma unroll
                for (int ct = 0; ct < 8; ct++) {
                    int dcol = 8 * ct + 2 * tc;
                    *(float2*)(og + (size_t)(t2 * 16 + tq) * DDIM + dcol) =
                        make_float2(oacc[t2][ct][0] * il, oacc[t2][ct][1] * il);
                    *(float2*)(og + (size_t)(t2 * 16 + tq + 8) * DDIM + dcol) =
                        make_float2(oacc[t2][ct][2] * ih, oacc[t2][ct][3] * ih);
                }
            }
        }

        j = (t << 3) + c1;
    }
}

extern "C" void kernel_launch(void* const* d_in, const int* in_sizes, int n_in,
                              void* d_out, int out_size) {
    (void)in_sizes; (void)n_in; (void)out_size;
    const float* q = (const float*)d_in[0];
    const float* k = (const float*)d_in[1];
    const float* v = (const float*)d_in[2];
    float* out = (float*)d_out;

    precompute_kv<<<1024, 256>>>(k, v);

    cudaFuncSetAttribute(poly_attn_mma,
                         cudaFuncAttributeMaxDynamicSharedMemorySize, SMEM_BYTES);
    poly_attn_mma<<<NCTAS, 256, SMEM_BYTES>>>(q, out);
}